// round 1
// baseline (speedup 1.0000x reference)
#include <cuda_runtime.h>
#include <math.h>

#define BATCH   32
#define W_GRID  640
#define H_GRID  480
#define IMG_H   480
#define IMG_W   640
#define NPIX    (BATCH * W_GRID * H_GRID)   // 9,830,400

// global scratch for the max reduction (ordered-uint encoding of float)
__device__ unsigned int g_max_bits;

// monotonic float<->uint mapping so atomicMax(unsigned) == float max
__device__ __forceinline__ unsigned int float_to_ordered(float f) {
    unsigned int u = __float_as_uint(f);
    return (u & 0x80000000u) ? ~u : (u | 0x80000000u);
}
__device__ __forceinline__ float ordered_to_float(unsigned int u) {
    unsigned int b = (u & 0x80000000u) ? (u ^ 0x80000000u) : ~u;
    return __uint_as_float(b);
}

__global__ void reset_kernel() { g_max_bits = 0u; }  // below every real float key

// 3x3 inverse via adjugate (matches jnp.linalg.inv to ~ulp for this well-conditioned K)
__device__ __forceinline__ void inv3x3(const float* __restrict__ K, float* Ki) {
    float a = K[0], b = K[1], c = K[2];
    float d = K[3], e = K[4], f = K[5];
    float g = K[6], h = K[7], i = K[8];
    float A  =  (e * i - f * h);
    float Bc = -(d * i - f * g);
    float C  =  (d * h - e * g);
    float det = a * A + b * Bc + c * C;
    Ki[0] = __fdiv_rn(A, det);
    Ki[1] = __fdiv_rn(-(b * i - c * h), det);
    Ki[2] = __fdiv_rn((b * f - c * e), det);
    Ki[3] = __fdiv_rn(Bc, det);
    Ki[4] = __fdiv_rn((a * i - c * g), det);
    Ki[5] = __fdiv_rn(-(a * f - c * d), det);
    Ki[6] = __fdiv_rn(C, det);
    Ki[7] = __fdiv_rn(-(a * h - b * g), det);
    Ki[8] = __fdiv_rn((a * e - b * d), det);
}

// Per-pixel reprojection, kept in the reference's op order (f32, IEEE div).
// u = h-index (gx), v = w-index (gy)  [meshgrid indexing='xy' quirk in the source]
__device__ __forceinline__ void compute_uv(
    int b, int wi, int hj,
    const float* __restrict__ depth,
    const float* __restrict__ T,
    const float* Ki, const float* __restrict__ K,
    float& uv0, float& uv1)
{
    float u = (float)hj;
    float v = (float)wi;
    float dpt = depth[((size_t)b * W_GRID + wi) * H_GRID + hj];

    // a = (u, v, 1) @ K^-1   (row-vector convention)
    float a0 = fmaf(u, Ki[0], fmaf(v, Ki[3], Ki[6]));
    float a1 = fmaf(u, Ki[1], fmaf(v, Ki[4], Ki[7]));
    float a2 = fmaf(u, Ki[2], fmaf(v, Ki[5], Ki[8]));

    float p0 = dpt * a0;
    float p1 = dpt * a1;
    float p2 = dpt * a2;

    const float* Tb = T + b * 16;
    // (p0,p1,p2,1) @ T, keep first 3
    float t0 = fmaf(p0, Tb[0], fmaf(p1, Tb[4], fmaf(p2, Tb[8],  Tb[12])));
    float t1 = fmaf(p0, Tb[1], fmaf(p1, Tb[5], fmaf(p2, Tb[9],  Tb[13])));
    float t2 = fmaf(p0, Tb[2], fmaf(p1, Tb[6], fmaf(p2, Tb[10], Tb[14])));

    // (t0,t1,t2) @ K
    float q0 = fmaf(t0, K[0], fmaf(t1, K[3], t2 * K[6]));
    float q1 = fmaf(t0, K[1], fmaf(t1, K[4], t2 * K[7]));
    float q2 = fmaf(t0, K[2], fmaf(t1, K[5], t2 * K[8]));

    float den = q2 + 1e-4f;
    uv0 = __fdiv_rn(q0, den);
    uv1 = __fdiv_rn(q1, den);
}

// Pass 1: global max of both uv components over all pixels.
__global__ void uv_max_kernel(
    const float* __restrict__ depth,
    const float* __restrict__ T,
    const float* __restrict__ K)
{
    float Ki[9];
    inv3x3(K, Ki);

    float local_max = -INFINITY;
    int stride = gridDim.x * blockDim.x;
    for (int idx = blockIdx.x * blockDim.x + threadIdx.x; idx < NPIX; idx += stride) {
        int hj = idx % H_GRID;
        int t  = idx / H_GRID;
        int wi = t % W_GRID;
        int b  = t / W_GRID;
        float uv0, uv1;
        compute_uv(b, wi, hj, depth, T, Ki, K, uv0, uv1);
        local_max = fmaxf(local_max, fmaxf(uv0, uv1));
    }

    // block reduction
    __shared__ float smax[256];
    int tid = threadIdx.x;
    smax[tid] = local_max;
    __syncthreads();
    for (int s = 128; s > 0; s >>= 1) {
        if (tid < s) smax[tid] = fmaxf(smax[tid], smax[tid + s]);
        __syncthreads();
    }
    if (tid == 0) {
        atomicMax(&g_max_bits, float_to_ordered(smax[0]));
    }
}

// Pass 2: recompute uv, normalize by global max, bilinear sample (zeros padding,
// align_corners=False), write [B, 3, W_GRID, H_GRID].
__global__ void sample_kernel(
    const float* __restrict__ depth,
    const float* __restrict__ T,
    const float* __restrict__ K,
    const float* __restrict__ image,
    float* __restrict__ out)
{
    int idx = blockIdx.x * blockDim.x + threadIdx.x;
    if (idx >= NPIX) return;

    int hj = idx % H_GRID;
    int t  = idx / H_GRID;
    int wi = t % W_GRID;
    int b  = t / W_GRID;

    float Ki[9];
    inv3x3(K, Ki);

    float uv0, uv1;
    compute_uv(b, wi, hj, depth, T, Ki, K, uv0, uv1);

    float gmax = ordered_to_float(g_max_bits);

    // uvn = 2*(uv/gmax) - 1
    float gn0 = fmaf(2.0f, __fdiv_rn(uv0, gmax), -1.0f);
    float gn1 = fmaf(2.0f, __fdiv_rn(uv1, gmax), -1.0f);

    // grid_sample coords (align_corners=False)
    float x = (gn0 + 1.0f) * (IMG_W * 0.5f) - 0.5f;
    float y = (gn1 + 1.0f) * (IMG_H * 0.5f) - 0.5f;

    float x0f = floorf(x);
    float y0f = floorf(y);
    float wx = x - x0f;
    float wy = y - y0f;
    float x1f = x0f + 1.0f;
    float y1f = y0f + 1.0f;

    // validity (float-domain compare, matches reference)
    float vx0 = (x0f >= 0.0f && x0f <= (float)(IMG_W - 1)) ? 1.0f : 0.0f;
    float vx1 = (x1f >= 0.0f && x1f <= (float)(IMG_W - 1)) ? 1.0f : 0.0f;
    float vy0 = (y0f >= 0.0f && y0f <= (float)(IMG_H - 1)) ? 1.0f : 0.0f;
    float vy1 = (y1f >= 0.0f && y1f <= (float)(IMG_H - 1)) ? 1.0f : 0.0f;

    // clipped integer indices (clip in float first to survive huge coords)
    int xi0 = (int)fminf(fmaxf(x0f, 0.0f), (float)(IMG_W - 1));
    int xi1 = (int)fminf(fmaxf(x1f, 0.0f), (float)(IMG_W - 1));
    int yi0 = (int)fminf(fmaxf(y0f, 0.0f), (float)(IMG_H - 1));
    int yi1 = (int)fminf(fmaxf(y1f, 0.0f), (float)(IMG_H - 1));

    float w00 = (1.0f - wx) * (1.0f - wy) * (vx0 * vy0);
    float w01 = wx * (1.0f - wy)          * (vx1 * vy0);
    float w10 = (1.0f - wx) * wy          * (vx0 * vy1);
    float w11 = wx * wy                   * (vx1 * vy1);

    size_t img_b = (size_t)b * 3 * IMG_H * IMG_W;
    int i00 = yi0 * IMG_W + xi0;
    int i01 = yi0 * IMG_W + xi1;
    int i10 = yi1 * IMG_W + xi0;
    int i11 = yi1 * IMG_W + xi1;

    size_t out_b = ((size_t)b * 3) * (size_t)(W_GRID * H_GRID) + (size_t)wi * H_GRID + hj;

    #pragma unroll
    for (int c = 0; c < 3; c++) {
        const float* ch = image + img_b + (size_t)c * (IMG_H * IMG_W);
        float v = w00 * ch[i00] + w01 * ch[i01] + w10 * ch[i10] + w11 * ch[i11];
        out[out_b + (size_t)c * (W_GRID * H_GRID)] = v;
    }
}

extern "C" void kernel_launch(void* const* d_in, const int* in_sizes, int n_in,
                              void* d_out, int out_size) {
    const float* depth = (const float*)d_in[0];   // [32, 640, 480, 1]
    const float* T     = (const float*)d_in[1];   // [32, 4, 4]
    const float* image = (const float*)d_in[2];   // [32, 3, 480, 640]
    const float* K     = (const float*)d_in[3];   // [3, 3]
    float* out = (float*)d_out;                   // [32, 3, 640, 480]

    reset_kernel<<<1, 1>>>();
    uv_max_kernel<<<148 * 8, 256>>>(depth, T, K);
    int blocks = (NPIX + 255) / 256;
    sample_kernel<<<blocks, 256>>>(depth, T, K, image, out);
}

// round 2
// speedup vs baseline: 2.1146x; 2.1146x over previous
#include <cuda_runtime.h>
#include <math.h>

#define BATCH   32
#define W_GRID  640
#define H_GRID  480
#define IMG_H   480
#define IMG_W   640
#define NPIX    (BATCH * W_GRID * H_GRID)   // 9,830,400
#define NGROUP  (NPIX / 4)                  // 2,457,600 4-pixel groups

// global scratch
__device__ unsigned int g_max_bits;
__device__ float g_Ki[9];

// monotonic float<->uint mapping so atomicMax(unsigned) == float max
__device__ __forceinline__ unsigned int float_to_ordered(float f) {
    unsigned int u = __float_as_uint(f);
    return (u & 0x80000000u) ? ~u : (u | 0x80000000u);
}
__device__ __forceinline__ float ordered_to_float(unsigned int u) {
    unsigned int b = (u & 0x80000000u) ? (u ^ 0x80000000u) : ~u;
    return __uint_as_float(b);
}

// init: reset max, compute K^-1 once (identical op order as before -> bit-identical Ki)
__global__ void init_kernel(const float* __restrict__ K) {
    g_max_bits = 0u;
    float a = K[0], b = K[1], c = K[2];
    float d = K[3], e = K[4], f = K[5];
    float g = K[6], h = K[7], i = K[8];
    float A  =  (e * i - f * h);
    float Bc = -(d * i - f * g);
    float C  =  (d * h - e * g);
    float det = a * A + b * Bc + c * C;
    g_Ki[0] = __fdiv_rn(A, det);
    g_Ki[1] = __fdiv_rn(-(b * i - c * h), det);
    g_Ki[2] = __fdiv_rn((b * f - c * e), det);
    g_Ki[3] = __fdiv_rn(Bc, det);
    g_Ki[4] = __fdiv_rn((a * i - c * g), det);
    g_Ki[5] = __fdiv_rn(-(a * f - c * d), det);
    g_Ki[6] = __fdiv_rn(C, det);
    g_Ki[7] = __fdiv_rn(-(a * h - b * g), det);
    g_Ki[8] = __fdiv_rn((a * e - b * d), det);
}

// Per-pixel reprojection, op order EXACTLY as the passing R1 kernel.
__device__ __forceinline__ void compute_uv(
    float u, float v, float dpt,
    const float* __restrict__ Tb,
    const float* Ki, const float* Kr,
    float& uv0, float& uv1)
{
    float a0 = fmaf(u, Ki[0], fmaf(v, Ki[3], Ki[6]));
    float a1 = fmaf(u, Ki[1], fmaf(v, Ki[4], Ki[7]));
    float a2 = fmaf(u, Ki[2], fmaf(v, Ki[5], Ki[8]));

    float p0 = dpt * a0;
    float p1 = dpt * a1;
    float p2 = dpt * a2;

    float t0 = fmaf(p0, Tb[0], fmaf(p1, Tb[4], fmaf(p2, Tb[8],  Tb[12])));
    float t1 = fmaf(p0, Tb[1], fmaf(p1, Tb[5], fmaf(p2, Tb[9],  Tb[13])));
    float t2 = fmaf(p0, Tb[2], fmaf(p1, Tb[6], fmaf(p2, Tb[10], Tb[14])));

    float q0 = fmaf(t0, Kr[0], fmaf(t1, Kr[3], t2 * Kr[6]));
    float q1 = fmaf(t0, Kr[1], fmaf(t1, Kr[4], t2 * Kr[7]));
    float q2 = fmaf(t0, Kr[2], fmaf(t1, Kr[5], t2 * Kr[8]));

    float den = q2 + 1e-4f;
    uv0 = __fdiv_rn(q0, den);
    uv1 = __fdiv_rn(q1, den);
}

// Pass 1: global max of both uv components over all pixels (4 px / iteration).
__global__ void uv_max_kernel(
    const float* __restrict__ depth,
    const float* __restrict__ T,
    const float* __restrict__ K)
{
    float Ki[9], Kr[9];
    #pragma unroll
    for (int i = 0; i < 9; i++) { Ki[i] = g_Ki[i]; Kr[i] = K[i]; }

    float local_max = -INFINITY;
    int stride = gridDim.x * blockDim.x;
    for (int g = blockIdx.x * blockDim.x + threadIdx.x; g < NGROUP; g += stride) {
        int hj4 = (g % (H_GRID / 4)) * 4;
        int t   = g / (H_GRID / 4);
        int wi  = t % W_GRID;
        int b   = t / W_GRID;

        float4 d4 = *reinterpret_cast<const float4*>(
            depth + ((size_t)b * W_GRID + wi) * H_GRID + hj4);
        const float* Tb = T + b * 16;
        float v = (float)wi;

        float dv[4] = {d4.x, d4.y, d4.z, d4.w};
        #pragma unroll
        for (int k = 0; k < 4; k++) {
            float uv0, uv1;
            compute_uv((float)(hj4 + k), v, dv[k], Tb, Ki, Kr, uv0, uv1);
            local_max = fmaxf(local_max, fmaxf(uv0, uv1));
        }
    }

    // warp reduction then block reduction
    #pragma unroll
    for (int off = 16; off > 0; off >>= 1)
        local_max = fmaxf(local_max, __shfl_xor_sync(0xffffffffu, local_max, off));

    __shared__ float smax[8];
    int warp = threadIdx.x >> 5;
    int lane = threadIdx.x & 31;
    if (lane == 0) smax[warp] = local_max;
    __syncthreads();
    if (warp == 0) {
        float m = (lane < (blockDim.x >> 5)) ? smax[lane] : -INFINITY;
        #pragma unroll
        for (int off = 4; off > 0; off >>= 1)
            m = fmaxf(m, __shfl_xor_sync(0xffffffffu, m, off));
        if (lane == 0) atomicMax(&g_max_bits, float_to_ordered(m));
    }
}

// Pass 2: recompute uv, normalize, bilinear sample, write [B,3,W,H]. 4 px/thread.
__global__ void sample_kernel(
    const float* __restrict__ depth,
    const float* __restrict__ T,
    const float* __restrict__ K,
    const float* __restrict__ image,
    float* __restrict__ out)
{
    int g = blockIdx.x * blockDim.x + threadIdx.x;
    if (g >= NGROUP) return;

    int hj4 = (g % (H_GRID / 4)) * 4;
    int t   = g / (H_GRID / 4);
    int wi  = t % W_GRID;
    int b   = t / W_GRID;

    float Ki[9], Kr[9];
    #pragma unroll
    for (int i = 0; i < 9; i++) { Ki[i] = g_Ki[i]; Kr[i] = K[i]; }

    float4 d4 = *reinterpret_cast<const float4*>(
        depth + ((size_t)b * W_GRID + wi) * H_GRID + hj4);
    const float* Tb = T + b * 16;
    float v = (float)wi;
    float gmax = ordered_to_float(g_max_bits);

    const float* img_b = image + (size_t)b * 3 * IMG_H * IMG_W;

    float r[3][4];   // [channel][pixel]
    float dv[4] = {d4.x, d4.y, d4.z, d4.w};

    #pragma unroll
    for (int k = 0; k < 4; k++) {
        float uv0, uv1;
        compute_uv((float)(hj4 + k), v, dv[k], Tb, Ki, Kr, uv0, uv1);

        float gn0 = fmaf(2.0f, __fdiv_rn(uv0, gmax), -1.0f);
        float gn1 = fmaf(2.0f, __fdiv_rn(uv1, gmax), -1.0f);

        float x = (gn0 + 1.0f) * (IMG_W * 0.5f) - 0.5f;
        float y = (gn1 + 1.0f) * (IMG_H * 0.5f) - 0.5f;

        float x0f = floorf(x);
        float y0f = floorf(y);
        float wx = x - x0f;
        float wy = y - y0f;
        float x1f = x0f + 1.0f;
        float y1f = y0f + 1.0f;

        float vx0 = (x0f >= 0.0f && x0f <= (float)(IMG_W - 1)) ? 1.0f : 0.0f;
        float vx1 = (x1f >= 0.0f && x1f <= (float)(IMG_W - 1)) ? 1.0f : 0.0f;
        float vy0 = (y0f >= 0.0f && y0f <= (float)(IMG_H - 1)) ? 1.0f : 0.0f;
        float vy1 = (y1f >= 0.0f && y1f <= (float)(IMG_H - 1)) ? 1.0f : 0.0f;

        int xi0 = (int)fminf(fmaxf(x0f, 0.0f), (float)(IMG_W - 1));
        int xi1 = (int)fminf(fmaxf(x1f, 0.0f), (float)(IMG_W - 1));
        int yi0 = (int)fminf(fmaxf(y0f, 0.0f), (float)(IMG_H - 1));
        int yi1 = (int)fminf(fmaxf(y1f, 0.0f), (float)(IMG_H - 1));

        float w00 = (1.0f - wx) * (1.0f - wy) * (vx0 * vy0);
        float w01 = wx * (1.0f - wy)          * (vx1 * vy0);
        float w10 = (1.0f - wx) * wy          * (vx0 * vy1);
        float w11 = wx * wy                   * (vx1 * vy1);

        int i00 = yi0 * IMG_W + xi0;
        int i01 = yi0 * IMG_W + xi1;
        int i10 = yi1 * IMG_W + xi0;
        int i11 = yi1 * IMG_W + xi1;

        #pragma unroll
        for (int c = 0; c < 3; c++) {
            const float* ch = img_b + (size_t)c * (IMG_H * IMG_W);
            r[c][k] = w00 * ch[i00] + w01 * ch[i01] + w10 * ch[i10] + w11 * ch[i11];
        }
    }

    size_t out_base = ((size_t)b * 3) * (size_t)(W_GRID * H_GRID)
                    + (size_t)wi * H_GRID + hj4;
    #pragma unroll
    for (int c = 0; c < 3; c++) {
        float4 o = make_float4(r[c][0], r[c][1], r[c][2], r[c][3]);
        *reinterpret_cast<float4*>(out + out_base + (size_t)c * (W_GRID * H_GRID)) = o;
    }
}

extern "C" void kernel_launch(void* const* d_in, const int* in_sizes, int n_in,
                              void* d_out, int out_size) {
    const float* depth = (const float*)d_in[0];   // [32, 640, 480, 1]
    const float* T     = (const float*)d_in[1];   // [32, 4, 4]
    const float* image = (const float*)d_in[2];   // [32, 3, 480, 640]
    const float* K     = (const float*)d_in[3];   // [3, 3]
    float* out = (float*)d_out;                   // [32, 3, 640, 480]

    init_kernel<<<1, 1>>>(K);
    uv_max_kernel<<<148 * 4, 256>>>(depth, T, K);
    int blocks = (NGROUP + 255) / 256;            // 9600
    sample_kernel<<<blocks, 256>>>(depth, T, K, image, out);
}